// round 8
// baseline (speedup 1.0000x reference)
#include <cuda_runtime.h>
#include <cstdint>

// 16 lanes/group, float4/lane, 4 edges/group, 20 gathers batched.
// __launch_bounds__(256,4) raises the register budget to 64/thread so ptxas
// can keep ~2x more gathers in flight (real MLP was reg-capped at 38 regs).
// Gather asm is non-volatile so the compiler may schedule/hoist freely.
// Folding butterfly reduction (15 shfls for 8 values); epilogue once per warp.
// Gathers: L2 evict_last. Output: evict-first streaming stores.

__device__ __forceinline__ float4 ldg_el(const float* p, uint64_t pol) {
    float4 v;
    asm("ld.global.nc.L2::cache_hint.v4.f32 {%0,%1,%2,%3}, [%4], %5;"
        : "=f"(v.x), "=f"(v.y), "=f"(v.z), "=f"(v.w)
        : "l"(p), "l"(pol));
    return v;
}

#define SHX(v, off) __shfl_xor_sync(0xFFFFFFFFu, (v), (off), 16)

__global__ void __launch_bounds__(256, 4) rpm_kernel(
    const float* __restrict__ G,
    const float* __restrict__ K,
    const float* __restrict__ Q,
    const float* __restrict__ V,
    const int* __restrict__ src,
    const int* __restrict__ dst,
    float* __restrict__ out,
    int n_edges,
    int n_nodes)
{
    uint64_t pol;
    asm("createpolicy.fractional.L2::evict_last.b64 %0, 1.0;" : "=l"(pol));

    int sub  = threadIdx.x >> 4;
    int lane = threadIdx.x & 15;
    int g    = blockIdx.x * (blockDim.x >> 4) + sub;
    int ebase = g * 4;

    int4 s4, d4;
    if (ebase + 3 < n_edges) {
        s4 = reinterpret_cast<const int4*>(src)[g];
        d4 = reinterpret_cast<const int4*>(dst)[g];
    } else {
        int ec0 = min(ebase + 0, n_edges - 1);
        int ec1 = min(ebase + 1, n_edges - 1);
        int ec2 = min(ebase + 2, n_edges - 1);
        int ec3 = min(ebase + 3, n_edges - 1);
        s4 = make_int4(src[ec0], src[ec1], src[ec2], src[ec3]);
        d4 = make_int4(dst[ec0], dst[ec1], dst[ec2], dst[ec3]);
    }

    size_t l4 = (size_t)lane * 4;

    // Reduction-feeding gathers first (G, K, Q)...
    float4 gs0 = ldg_el(G + (size_t)s4.x * 64 + l4, pol);
    float4 gd0 = ldg_el(G + (size_t)d4.x * 64 + l4, pol);
    float4 ks0 = ldg_el(K + (size_t)s4.x * 64 + l4, pol);
    float4 qd0 = ldg_el(Q + (size_t)d4.x * 64 + l4, pol);
    float4 gs1 = ldg_el(G + (size_t)s4.y * 64 + l4, pol);
    float4 gd1 = ldg_el(G + (size_t)d4.y * 64 + l4, pol);
    float4 ks1 = ldg_el(K + (size_t)s4.y * 64 + l4, pol);
    float4 qd1 = ldg_el(Q + (size_t)d4.y * 64 + l4, pol);
    float4 gs2 = ldg_el(G + (size_t)s4.z * 64 + l4, pol);
    float4 gd2 = ldg_el(G + (size_t)d4.z * 64 + l4, pol);
    float4 ks2 = ldg_el(K + (size_t)s4.z * 64 + l4, pol);
    float4 qd2 = ldg_el(Q + (size_t)d4.z * 64 + l4, pol);
    float4 gs3 = ldg_el(G + (size_t)s4.w * 64 + l4, pol);
    float4 gd3 = ldg_el(G + (size_t)d4.w * 64 + l4, pol);
    float4 ks3 = ldg_el(K + (size_t)s4.w * 64 + l4, pol);
    float4 qd3 = ldg_el(Q + (size_t)d4.w * 64 + l4, pol);
    // ...V gathers last: only consumed at the store, so their latency hides
    // under the whole reduction + epilogue.
    float4 vs0 = ldg_el(V + (size_t)s4.x * 64 + l4, pol);
    float4 vs1 = ldg_el(V + (size_t)s4.y * 64 + l4, pol);
    float4 vs2 = ldg_el(V + (size_t)s4.z * 64 + l4, pol);
    float4 vs3 = ldg_el(V + (size_t)s4.w * 64 + l4, pol);

    float dx, dy, dz, dw;
    dx = gs0.x-gd0.x; dy = gs0.y-gd0.y; dz = gs0.z-gd0.z; dw = gs0.w-gd0.w;
    float pd0 = dx*dx + dy*dy + dz*dz + dw*dw;
    float pk0 = ks0.x*qd0.x + ks0.y*qd0.y + ks0.z*qd0.z + ks0.w*qd0.w;
    dx = gs1.x-gd1.x; dy = gs1.y-gd1.y; dz = gs1.z-gd1.z; dw = gs1.w-gd1.w;
    float pd1 = dx*dx + dy*dy + dz*dz + dw*dw;
    float pk1 = ks1.x*qd1.x + ks1.y*qd1.y + ks1.z*qd1.z + ks1.w*qd1.w;
    dx = gs2.x-gd2.x; dy = gs2.y-gd2.y; dz = gs2.z-gd2.z; dw = gs2.w-gd2.w;
    float pd2 = dx*dx + dy*dy + dz*dz + dw*dw;
    float pk2 = ks2.x*qd2.x + ks2.y*qd2.y + ks2.z*qd2.z + ks2.w*qd2.w;
    dx = gs3.x-gd3.x; dy = gs3.y-gd3.y; dz = gs3.z-gd3.z; dw = gs3.w-gd3.w;
    float pd3 = dx*dx + dy*dy + dz*dz + dw*dw;
    float pk3 = ks3.x*qd3.x + ks3.y*qd3.y + ks3.z*qd3.z + ks3.w*qd3.w;

    // ---- folding reduction: 8 values over 16 lanes ----
    pd0 += SHX(pd0, 8);  pk0 += SHX(pk0, 8);
    pd1 += SHX(pd1, 8);  pk1 += SHX(pk1, 8);
    pd2 += SHX(pd2, 8);  pk2 += SHX(pk2, 8);
    pd3 += SHX(pd3, 8);  pk3 += SHX(pk3, 8);
    bool h8 = (lane & 8) != 0;
    float y0 = h8 ? pk0 : pd0;
    float y1 = h8 ? pk1 : pd1;
    float y2 = h8 ? pk2 : pd2;
    float y3 = h8 ? pk3 : pd3;
    y0 += SHX(y0, 4);  y1 += SHX(y1, 4);  y2 += SHX(y2, 4);  y3 += SHX(y3, 4);
    bool h4 = (lane & 4) != 0;
    float z0 = h4 ? y1 : y0;
    float z1 = h4 ? y3 : y2;
    z0 += SHX(z0, 2);  z1 += SHX(z1, 2);
    bool h2 = (lane & 2) != 0;
    float u = h2 ? z1 : z0;
    u += SHX(u, 1);
    float t = SHX(u, 8);
    float pdv = h8 ? t : u;
    float pkv = h8 ? u : t;

    const float isd = 0.125f;  // 1/sqrt(64)
    float a = fminf(fmaxf(-sqrtf(pdv + 1e-6f) * isd, -5.0f), 5.0f);
    float b = fminf(fmaxf(pkv * isd, -5.0f), 5.0f);
    float w = __expf(a + b);

    float w0 = __shfl_sync(0xFFFFFFFFu, w, 0, 16);
    float w1 = __shfl_sync(0xFFFFFFFFu, w, 4, 16);
    float w2 = __shfl_sync(0xFFFFFFFFu, w, 2, 16);
    float w3 = __shfl_sync(0xFFFFFFFFu, w, 6, 16);

    float4* out4 = reinterpret_cast<float4*>(out);
    if (ebase + 0 < n_edges)
        __stcs(&out4[(size_t)(ebase + 0) * 16 + lane],
               make_float4(w0*vs0.x, w0*vs0.y, w0*vs0.z, w0*vs0.w));
    if (ebase + 1 < n_edges)
        __stcs(&out4[(size_t)(ebase + 1) * 16 + lane],
               make_float4(w1*vs1.x, w1*vs1.y, w1*vs1.z, w1*vs1.w));
    if (ebase + 2 < n_edges)
        __stcs(&out4[(size_t)(ebase + 2) * 16 + lane],
               make_float4(w2*vs2.x, w2*vs2.y, w2*vs2.z, w2*vs2.w));
    if (ebase + 3 < n_edges)
        __stcs(&out4[(size_t)(ebase + 3) * 16 + lane],
               make_float4(w3*vs3.x, w3*vs3.y, w3*vs3.z, w3*vs3.w));
}

extern "C" void kernel_launch(void* const* d_in, const int* in_sizes, int n_in,
                              void* d_out, int out_size) {
    const float* G = (const float*)d_in[0];
    const float* K = (const float*)d_in[1];
    const float* Q = (const float*)d_in[2];
    const float* V = (const float*)d_in[3];
    const int* src = (const int*)d_in[4];
    const int* dst = (const int*)d_in[5];
    float* out = (float*)d_out;

    int n_edges = in_sizes[4];
    int n_nodes = in_sizes[0] / 64;
    int groups_per_block = 256 / 16;
    int edges_per_block = groups_per_block * 4;   // 64 edges/block
    int blocks = (n_edges + edges_per_block - 1) / edges_per_block;
    rpm_kernel<<<blocks, 256>>>(G, K, Q, V, src, dst, out, n_edges, n_nodes);
}

// round 9
// speedup vs baseline: 1.1793x; 1.1793x over previous
#include <cuda_runtime.h>
#include <cstdint>

// R7 structure (best: 87.5us) with 128-thread CTAs for finer scheduling
// granularity: 16 lanes/group, float4/lane, 4 edges/group, 20 gathers batched,
// folding butterfly reduction (15 shfls for 8 values), epilogue once per warp.
// launch_bounds(128,12): 12 CTAs x 4 warps = 48 warps/SM theoretical, same as
// R7's ceiling but with 2x more independent CTAs to smooth wave drain.
// Gathers: L2 evict_last. Output: evict-first streaming stores.

__device__ __forceinline__ float4 ldg_el(const float* p, uint64_t pol) {
    float4 v;
    asm volatile(
        "ld.global.nc.L2::cache_hint.v4.f32 {%0,%1,%2,%3}, [%4], %5;"
        : "=f"(v.x), "=f"(v.y), "=f"(v.z), "=f"(v.w)
        : "l"(p), "l"(pol));
    return v;
}

#define SHX(v, off) __shfl_xor_sync(0xFFFFFFFFu, (v), (off), 16)

__global__ void __launch_bounds__(128, 12) rpm_kernel(
    const float* __restrict__ G,
    const float* __restrict__ K,
    const float* __restrict__ Q,
    const float* __restrict__ V,
    const int* __restrict__ src,
    const int* __restrict__ dst,
    float* __restrict__ out,
    int n_edges,
    int n_nodes)
{
    uint64_t pol;
    asm("createpolicy.fractional.L2::evict_last.b64 %0, 1.0;" : "=l"(pol));

    int sub  = threadIdx.x >> 4;
    int lane = threadIdx.x & 15;
    int g    = blockIdx.x * (blockDim.x >> 4) + sub;
    int ebase = g * 4;

    int4 s4, d4;
    if (ebase + 3 < n_edges) {
        s4 = reinterpret_cast<const int4*>(src)[g];
        d4 = reinterpret_cast<const int4*>(dst)[g];
    } else {
        int ec0 = min(ebase + 0, n_edges - 1);
        int ec1 = min(ebase + 1, n_edges - 1);
        int ec2 = min(ebase + 2, n_edges - 1);
        int ec3 = min(ebase + 3, n_edges - 1);
        s4 = make_int4(src[ec0], src[ec1], src[ec2], src[ec3]);
        d4 = make_int4(dst[ec0], dst[ec1], dst[ec2], dst[ec3]);
    }

    size_t l4 = (size_t)lane * 4;

    // 20 batched gathers (order as in R7 — proven schedule).
    float4 gs0 = ldg_el(G + (size_t)s4.x * 64 + l4, pol);
    float4 gd0 = ldg_el(G + (size_t)d4.x * 64 + l4, pol);
    float4 ks0 = ldg_el(K + (size_t)s4.x * 64 + l4, pol);
    float4 qd0 = ldg_el(Q + (size_t)d4.x * 64 + l4, pol);
    float4 vs0 = ldg_el(V + (size_t)s4.x * 64 + l4, pol);
    float4 gs1 = ldg_el(G + (size_t)s4.y * 64 + l4, pol);
    float4 gd1 = ldg_el(G + (size_t)d4.y * 64 + l4, pol);
    float4 ks1 = ldg_el(K + (size_t)s4.y * 64 + l4, pol);
    float4 qd1 = ldg_el(Q + (size_t)d4.y * 64 + l4, pol);
    float4 vs1 = ldg_el(V + (size_t)s4.y * 64 + l4, pol);
    float4 gs2 = ldg_el(G + (size_t)s4.z * 64 + l4, pol);
    float4 gd2 = ldg_el(G + (size_t)d4.z * 64 + l4, pol);
    float4 ks2 = ldg_el(K + (size_t)s4.z * 64 + l4, pol);
    float4 qd2 = ldg_el(Q + (size_t)d4.z * 64 + l4, pol);
    float4 vs2 = ldg_el(V + (size_t)s4.z * 64 + l4, pol);
    float4 gs3 = ldg_el(G + (size_t)s4.w * 64 + l4, pol);
    float4 gd3 = ldg_el(G + (size_t)d4.w * 64 + l4, pol);
    float4 ks3 = ldg_el(K + (size_t)s4.w * 64 + l4, pol);
    float4 qd3 = ldg_el(Q + (size_t)d4.w * 64 + l4, pol);
    float4 vs3 = ldg_el(V + (size_t)s4.w * 64 + l4, pol);

    float dx, dy, dz, dw;
    dx = gs0.x-gd0.x; dy = gs0.y-gd0.y; dz = gs0.z-gd0.z; dw = gs0.w-gd0.w;
    float pd0 = dx*dx + dy*dy + dz*dz + dw*dw;
    float pk0 = ks0.x*qd0.x + ks0.y*qd0.y + ks0.z*qd0.z + ks0.w*qd0.w;
    dx = gs1.x-gd1.x; dy = gs1.y-gd1.y; dz = gs1.z-gd1.z; dw = gs1.w-gd1.w;
    float pd1 = dx*dx + dy*dy + dz*dz + dw*dw;
    float pk1 = ks1.x*qd1.x + ks1.y*qd1.y + ks1.z*qd1.z + ks1.w*qd1.w;
    dx = gs2.x-gd2.x; dy = gs2.y-gd2.y; dz = gs2.z-gd2.z; dw = gs2.w-gd2.w;
    float pd2 = dx*dx + dy*dy + dz*dz + dw*dw;
    float pk2 = ks2.x*qd2.x + ks2.y*qd2.y + ks2.z*qd2.z + ks2.w*qd2.w;
    dx = gs3.x-gd3.x; dy = gs3.y-gd3.y; dz = gs3.z-gd3.z; dw = gs3.w-gd3.w;
    float pd3 = dx*dx + dy*dy + dz*dz + dw*dw;
    float pk3 = ks3.x*qd3.x + ks3.y*qd3.y + ks3.z*qd3.z + ks3.w*qd3.w;

    // ---- folding reduction: 8 values over 16 lanes ----
    pd0 += SHX(pd0, 8);  pk0 += SHX(pk0, 8);
    pd1 += SHX(pd1, 8);  pk1 += SHX(pk1, 8);
    pd2 += SHX(pd2, 8);  pk2 += SHX(pk2, 8);
    pd3 += SHX(pd3, 8);  pk3 += SHX(pk3, 8);
    bool h8 = (lane & 8) != 0;
    float y0 = h8 ? pk0 : pd0;
    float y1 = h8 ? pk1 : pd1;
    float y2 = h8 ? pk2 : pd2;
    float y3 = h8 ? pk3 : pd3;
    y0 += SHX(y0, 4);  y1 += SHX(y1, 4);  y2 += SHX(y2, 4);  y3 += SHX(y3, 4);
    bool h4 = (lane & 4) != 0;
    float z0 = h4 ? y1 : y0;
    float z1 = h4 ? y3 : y2;
    z0 += SHX(z0, 2);  z1 += SHX(z1, 2);
    bool h2 = (lane & 2) != 0;
    float u = h2 ? z1 : z0;
    u += SHX(u, 1);
    float t = SHX(u, 8);
    float pdv = h8 ? t : u;
    float pkv = h8 ? u : t;

    const float isd = 0.125f;  // 1/sqrt(64)
    float a = fminf(fmaxf(-sqrtf(pdv + 1e-6f) * isd, -5.0f), 5.0f);
    float b = fminf(fmaxf(pkv * isd, -5.0f), 5.0f);
    float w = __expf(a + b);

    float w0 = __shfl_sync(0xFFFFFFFFu, w, 0, 16);
    float w1 = __shfl_sync(0xFFFFFFFFu, w, 4, 16);
    float w2 = __shfl_sync(0xFFFFFFFFu, w, 2, 16);
    float w3 = __shfl_sync(0xFFFFFFFFu, w, 6, 16);

    float4* out4 = reinterpret_cast<float4*>(out);
    if (ebase + 0 < n_edges)
        __stcs(&out4[(size_t)(ebase + 0) * 16 + lane],
               make_float4(w0*vs0.x, w0*vs0.y, w0*vs0.z, w0*vs0.w));
    if (ebase + 1 < n_edges)
        __stcs(&out4[(size_t)(ebase + 1) * 16 + lane],
               make_float4(w1*vs1.x, w1*vs1.y, w1*vs1.z, w1*vs1.w));
    if (ebase + 2 < n_edges)
        __stcs(&out4[(size_t)(ebase + 2) * 16 + lane],
               make_float4(w2*vs2.x, w2*vs2.y, w2*vs2.z, w2*vs2.w));
    if (ebase + 3 < n_edges)
        __stcs(&out4[(size_t)(ebase + 3) * 16 + lane],
               make_float4(w3*vs3.x, w3*vs3.y, w3*vs3.z, w3*vs3.w));
}

extern "C" void kernel_launch(void* const* d_in, const int* in_sizes, int n_in,
                              void* d_out, int out_size) {
    const float* G = (const float*)d_in[0];
    const float* K = (const float*)d_in[1];
    const float* Q = (const float*)d_in[2];
    const float* V = (const float*)d_in[3];
    const int* src = (const int*)d_in[4];
    const int* dst = (const int*)d_in[5];
    float* out = (float*)d_out;

    int n_edges = in_sizes[4];
    int n_nodes = in_sizes[0] / 64;
    int groups_per_block = 128 / 16;              // 8 groups
    int edges_per_block = groups_per_block * 4;   // 32 edges/block
    int blocks = (n_edges + edges_per_block - 1) / edges_per_block;
    rpm_kernel<<<blocks, 128>>>(G, K, Q, V, src, dst, out, n_edges, n_nodes);
}